// round 11
// baseline (speedup 1.0000x reference)
#include <cuda_runtime.h>

#define BATCH   16
#define HW      1048576u
#define HW4     262144u          // HW / 4
// score s in [0.75, 4.25] -> float bits in [0x3F400000, 0x40880000]
#define B1_MIN  259072u          // 0x3F400000 >> 12
#define B1_BINS 5249             // (0x40880 - 0x3F400) + 1
#define CAND_CAP 32768
#define BT   256
#define BPB  32                  // blocks per batch
#define NBLK (BATCH * BPB)       // 512 total blocks — must all be co-resident
#define SENT 0xFFFFFFFFu

__device__ unsigned g_hist[BATCH][B1_BINS];
__device__ unsigned g_np[BATCH];
__device__ unsigned g_cnt[BATCH];
__device__ uint2    g_cand[BATCH][CAND_CAP];   // x = key bits, y = idx in batch
__device__ unsigned g_T[BATCH];                // threshold level-1 bin (or SENT)
__device__ unsigned g_k1[BATCH];               // quota inside threshold bin
__device__ unsigned g_ntr[BATCH];
__device__ double   g_loss;
__device__ unsigned g_barcnt;                  // grid barrier arrive counter
__device__ unsigned g_bargen;                  // grid barrier generation

__device__ __forceinline__ unsigned score_key(float p, int m) {
    // bit-exact reproduction of the JAX f32 score
    float gt    = (float)m;
    float conf  = fmaxf(p, 1.0f - p);
    bool  corr  = (p > 0.5f) == (gt == 1.0f);
    bool  isc   = conf > 0.85f;
    float score = corr ? (isc ? 1.0f : 2.0f) : (isc ? 4.0f : 3.0f);
    float bonus = (conf - 0.5f) * 0.5f;      // exact in f32
    float s     = corr ? (score - bonus) : (score + bonus);
    return __float_as_uint(s);               // s > 0 => uint order == float order
}

// Grid-wide barrier. Safe because all NBLK blocks are co-resident
// (512 blocks, 4/SM worst case: 1024 thr, <=43K regs, ~113KB smem per SM).
__device__ __forceinline__ void gsync() {
    __syncthreads();
    if (threadIdx.x == 0) {
        unsigned gen = *(volatile unsigned*)&g_bargen;
        __threadfence();
        if (atomicAdd(&g_barcnt, 1u) == NBLK - 1u) {
            g_barcnt = 0u;
            __threadfence();
            atomicAdd(&g_bargen, 1u);      // release next generation
        } else {
            while (*(volatile unsigned*)&g_bargen == gen) __nanosleep(64);
        }
        __threadfence();
    }
    __syncthreads();
}

__global__ __launch_bounds__(BT, 6) void k_all(const float4* __restrict__ pred,
                                               const int4* __restrict__ mask,
                                               float* __restrict__ out) {
    // shared overlay (28.2KB): hist phase uses S[0..B1_BINS]; refine phase
    // uses h2=S[0..4095], scan=S[4096..4351], eq=S[4352..6399], vars=S[6400..]
    __shared__ unsigned S[7040];
    __shared__ double   w8[8];
    const int bid = blockIdx.x, t = threadIdx.x;
    const int b = bid / BPB, sub = bid % BPB;
    const unsigned gtid = (unsigned)bid * BT + t;
    const int lane = t & 31, warp = t >> 5;

    // ── phase 0: zero all cross-phase state (replay-safe) ──
    for (unsigned i = gtid; i < BATCH * B1_BINS; i += NBLK * BT)
        (&g_hist[0][0])[i] = 0u;
    if (gtid < BATCH) { g_np[gtid] = 0u; g_cnt[gtid] = 0u; }
    if (gtid == 0) g_loss = 0.0;
    gsync();

    // ── phase 1: histogram of level-1 bins ──
    {
        for (int i = t; i < B1_BINS; i += BT) S[i] = 0u;
        if (t == 0) S[B1_BINS] = 0u;
        __syncthreads();
        const float4* P = pred + (size_t)b * HW4;
        const int4*   M = mask + (size_t)b * HW4;
        unsigned localn = 0;
        for (unsigned v = sub * (BT * 2) + t; v < HW4; v += BT * 2 * BPB) {
            int4   ma = M[v];
            float4 pa = P[v];
            int4   mb = M[v + BT];
            float4 pb = P[v + BT];
            if (ma.x != 2) { localn++; atomicAdd(&S[(score_key(pa.x, ma.x) >> 12) - B1_MIN], 1u); }
            if (ma.y != 2) { localn++; atomicAdd(&S[(score_key(pa.y, ma.y) >> 12) - B1_MIN], 1u); }
            if (ma.z != 2) { localn++; atomicAdd(&S[(score_key(pa.z, ma.z) >> 12) - B1_MIN], 1u); }
            if (ma.w != 2) { localn++; atomicAdd(&S[(score_key(pa.w, ma.w) >> 12) - B1_MIN], 1u); }
            if (mb.x != 2) { localn++; atomicAdd(&S[(score_key(pb.x, mb.x) >> 12) - B1_MIN], 1u); }
            if (mb.y != 2) { localn++; atomicAdd(&S[(score_key(pb.y, mb.y) >> 12) - B1_MIN], 1u); }
            if (mb.z != 2) { localn++; atomicAdd(&S[(score_key(pb.z, mb.z) >> 12) - B1_MIN], 1u); }
            if (mb.w != 2) { localn++; atomicAdd(&S[(score_key(pb.w, mb.w) >> 12) - B1_MIN], 1u); }
        }
        atomicAdd(&S[B1_BINS], localn);
        __syncthreads();
        for (int i = t; i < B1_BINS; i += BT) {
            unsigned v = S[i];
            if (v) atomicAdd(&g_hist[b][i], v);
        }
        if (t == 0) atomicAdd(&g_np[b], S[B1_BINS]);
    }
    gsync();

    // ── phase 2: per-batch selection (one block per batch) ──
    if (sub == 0) {
        const int PB = 21;               // 256*21 >= 5249
        unsigned hv[PB];
        unsigned local = 0;
        #pragma unroll
        for (int j = 0; j < PB; j++) {
            int pos = t * PB + j;
            hv[j] = (pos < B1_BINS) ? g_hist[b][B1_BINS - 1 - pos] : 0u;  // descending
            local += hv[j];
        }
        S[t] = local; __syncthreads();
        for (int off = 1; off < 256; off <<= 1) {
            unsigned v = (t >= off) ? S[t - off] : 0u;
            __syncthreads();
            S[t] += v;
            __syncthreads();
        }
        unsigned before = S[t] - local;
        unsigned np  = g_np[b];
        unsigned ntr = (unsigned)(int)((float)np * 0.5f);  // matches (f32(n)*0.5).astype(i32)
        if (t == 0) g_ntr[b] = ntr;
        if (ntr == 0) {
            if (t == 0) { g_T[b] = SENT; g_k1[b] = 0u; }
        } else if (before < ntr && before + local >= ntr) {
            unsigned acc = before;
            #pragma unroll
            for (int j = 0; j < PB; j++) {
                int pos = t * PB + j;
                if (pos >= B1_BINS) break;
                if (acc + hv[j] >= ntr) {
                    g_T[b]  = (unsigned)(B1_BINS - 1 - pos);
                    g_k1[b] = ntr - acc;
                    break;
                }
                acc += hv[j];
            }
        }
    }
    gsync();

    // ── phase 3: main sweep — definite masks + BCE; bin==T -> candidates ──
    {
        unsigned T = g_T[b];             // SENT => everything annotated is holdout
        const float4* P = pred + (size_t)b * HW4;
        const int4*   M = mask + (size_t)b * HW4;
        float* outT = out + 1 + (size_t)b * HW;
        float* outH = out + 1 + (size_t)BATCH * HW + (size_t)b * HW;

        double acc = 0.0;
        for (unsigned v = sub * (BT * 2) + t; v < HW4; v += BT * 2 * BPB) {
            int4   m4[2];
            float4 p4[2];
            m4[0] = M[v];      p4[0] = P[v];
            m4[1] = M[v + BT]; p4[1] = P[v + BT];
            #pragma unroll
            for (int h = 0; h < 2; h++) {
                unsigned base = (v + h * BT) * 4u;
                #pragma unroll
                for (int k = 0; k < 4; k++) {
                    int   m = (k == 0) ? m4[h].x : (k == 1) ? m4[h].y : (k == 2) ? m4[h].z : m4[h].w;
                    float p = (k == 0) ? p4[h].x : (k == 1) ? p4[h].y : (k == 2) ? p4[h].z : p4[h].w;
                    if (m == 2) {
                        __stcs(&outT[base + k], 0.0f);
                        __stcs(&outH[base + k], 0.0f);
                        continue;
                    }
                    unsigned key = score_key(p, m);
                    unsigned bin = (key >> 12) - B1_MIN;
                    if (bin == T) {      // sparse: resolved in phase 4
                        unsigned pos = atomicAdd(&g_cnt[b], 1u);
                        if (pos < CAND_CAP) g_cand[b][pos] = make_uint2(key, base + k);
                        continue;
                    }
                    bool train = bin > T;
                    __stcs(&outT[base + k], train ? 1.0f : 0.0f);
                    __stcs(&outH[base + k], train ? 0.0f : 1.0f);
                    if (train) {
                        float pc = fminf(fmaxf(p, 1e-7f), 1.0f - 1e-7f);
                        acc += (double)((m == 1) ? -logf(pc) : -logf(1.0f - pc));
                    }
                }
            }
        }
        #pragma unroll
        for (int off = 16; off; off >>= 1)
            acc += __shfl_down_sync(0xFFFFFFFFu, acc, off);
        if (lane == 0) w8[warp] = acc;
        __syncthreads();
        if (t == 0) {
            double s2 = 0.0;
            #pragma unroll
            for (int i = 0; i < 8; i++) s2 += w8[i];
            atomicAdd(&g_loss, s2);
        }
    }
    gsync();

    // ── phase 4: refine bin T, fix up candidates (one block per batch) ──
    if (sub == 0) {
        unsigned T = g_T[b];
        double acc = 0.0;
        if (T != SENT) {
            unsigned* h2 = S;            // 4096
            unsigned* sc = S + 4096;     // 256
            unsigned* eq = S + 4352;     // 2048
            // vars: S[6400]=eqc S[6401]=V S[6402]=keq S[6403]=meq S[6404]=ic
            unsigned k1 = g_k1[b];
            unsigned nc = min(g_cnt[b], (unsigned)CAND_CAP);
            for (int i = t; i < 4096; i += 256) h2[i] = 0u;
            if (t == 0) {
                S[6400] = 0u;
                S[6401] = (T + B1_MIN) << 12;   // fallback V
                S[6402] = 0u; S[6403] = 0u; S[6404] = SENT;
            }
            __syncthreads();
            for (unsigned i = t; i < nc; i += 256)
                atomicAdd(&h2[g_cand[b][i].x & 0xFFFu], 1u);
            __syncthreads();

            const int PB = 16;
            unsigned local = 0;
            #pragma unroll
            for (int j = 0; j < PB; j++) local += h2[4095 - (t * PB + j)];
            sc[t] = local; __syncthreads();
            for (int off = 1; off < 256; off <<= 1) {
                unsigned v = (t >= off) ? sc[t - off] : 0u;
                __syncthreads();
                sc[t] += v;
                __syncthreads();
            }
            unsigned before = sc[t] - local;
            if (before < k1 && before + local >= k1) {
                unsigned a2 = before;
                for (int j = 0; j < PB; j++) {
                    int v = 4095 - (t * PB + j);
                    unsigned h = h2[v];
                    if (a2 + h >= k1) {
                        S[6401] = ((T + B1_MIN) << 12) | (unsigned)v;
                        S[6402] = k1 - a2; S[6403] = h;
                        break;
                    }
                    a2 += h;
                }
            }
            __syncthreads();
            unsigned V = S[6401], keq = S[6402], meq = S[6403];
            if (keq != meq && meq != 0u) {
                // index tie-break among key==V (stable argsort: low idx wins)
                for (unsigned i = t; i < nc; i += 256) {
                    if (g_cand[b][i].x == V) {
                        unsigned p = atomicAdd(&S[6400], 1u);
                        if (p < 2048u) eq[p] = g_cand[b][i].y;
                    }
                }
                __syncthreads();
                unsigned mm = min(S[6400], 2048u);
                if (keq < mm) {
                    for (unsigned i = t; i < mm; i += 256) {
                        unsigned x = eq[i], r = 0;
                        for (unsigned j = 0; j < mm; j++) r += (eq[j] < x) ? 1u : 0u;
                        if (r == keq) S[6404] = x;
                    }
                }
                __syncthreads();
            }
            unsigned ic = S[6404];
            const float* Ps = (const float*)pred + (size_t)b * HW;
            const int*   Ms = (const int*)mask + (size_t)b * HW;
            float* outT = out + 1 + (size_t)b * HW;
            float* outH = out + 1 + (size_t)BATCH * HW + (size_t)b * HW;
            for (unsigned i = t; i < nc; i += 256) {
                uint2 c = g_cand[b][i];
                bool train = (c.x > V) || (c.x == V && c.y < ic);
                outT[c.y] = train ? 1.0f : 0.0f;
                outH[c.y] = train ? 0.0f : 1.0f;
                if (train) {
                    float p = Ps[c.y];
                    int   m = Ms[c.y];
                    float pc = fminf(fmaxf(p, 1e-7f), 1.0f - 1e-7f);
                    acc += (double)((m == 1) ? -logf(pc) : -logf(1.0f - pc));
                }
            }
        }
        #pragma unroll
        for (int off = 16; off; off >>= 1)
            acc += __shfl_down_sync(0xFFFFFFFFu, acc, off);
        if (lane == 0) w8[warp] = acc;
        __syncthreads();
        if (t == 0) {
            double s2 = 0.0;
            #pragma unroll
            for (int i = 0; i < 8; i++) s2 += w8[i];
            if (s2 != 0.0) atomicAdd(&g_loss, s2);
        }
    }
    gsync();

    // ── phase 5: finalize scalar loss ──
    if (gtid == 0) {
        unsigned tot = 0;
        #pragma unroll
        for (int i = 0; i < BATCH; i++) tot += g_ntr[i];
        out[0] = (float)g_loss / ((float)tot + 1e-7f);
    }
}

extern "C" void kernel_launch(void* const* d_in, const int* in_sizes, int n_in,
                              void* d_out, int out_size) {
    const float4* pred = (const float4*)d_in[0];
    const int4*   mask = (const int4*)d_in[1];
    float* out = (float*)d_out;
    k_all<<<NBLK, BT>>>(pred, mask, out);
}

// round 15
// speedup vs baseline: 1.2993x; 1.2993x over previous
#include <cuda_runtime.h>

#define BATCH   16
#define HW      1048576u
#define HW4     262144u          // HW / 4
// score s in [0.75, 4.25] -> float bits in [0x3F400000, 0x40880000]
#define B1_MIN  259072u          // 0x3F400000 >> 12
#define B1_BINS 5249             // (0x40880 - 0x3F400) + 1
#define CAND_CAP 32768
#define BT  256
#define GXH 64                   // hist blocks per batch
#define GXM 128                  // main-pass blocks per batch
#define SENT 0xFFFFFFFFu

// __device__ globals are zero-initialized at load; every consumer resets what
// it reads so graph replays are deterministic.
__device__ unsigned g_hist[BATCH][B1_BINS];
__device__ unsigned g_np[BATCH];
__device__ unsigned g_cnt[BATCH];
__device__ uint2    g_cand[BATCH][CAND_CAP];   // x = key bits, y = idx in batch
__device__ unsigned g_T[BATCH];                // threshold level-1 bin (or SENT)
__device__ unsigned g_k1[BATCH];               // quota inside threshold bin
__device__ unsigned g_ntr[BATCH];
__device__ double   g_loss;
__device__ unsigned g_done;

__device__ __forceinline__ unsigned score_key(float p, int m) {
    // bit-exact reproduction of the JAX f32 score
    float gt    = (float)m;
    float conf  = fmaxf(p, 1.0f - p);
    bool  corr  = (p > 0.5f) == (gt == 1.0f);
    bool  isc   = conf > 0.85f;
    float score = corr ? (isc ? 1.0f : 2.0f) : (isc ? 4.0f : 3.0f);
    float bonus = (conf - 0.5f) * 0.5f;      // exact in f32
    float s     = corr ? (score - bonus) : (score + bonus);
    return __float_as_uint(s);               // s > 0 => uint order == float order
}

// ─── pass 1: per-batch level-1 histogram ────────────────────────────────────
__global__ __launch_bounds__(BT) void k_hist(const float4* __restrict__ pred,
                                             const int4* __restrict__ mask) {
    __shared__ unsigned sh[B1_BINS];
    __shared__ unsigned scnt;
    int b = blockIdx.y;
    int t = threadIdx.x;
    for (int i = t; i < B1_BINS; i += BT) sh[i] = 0u;
    if (t == 0) scnt = 0u;
    __syncthreads();

    const float4* P = pred + (size_t)b * HW4;
    const int4*   M = mask + (size_t)b * HW4;
    unsigned localn = 0;
    for (unsigned v = blockIdx.x * (BT * 2) + t; v < HW4; v += BT * 2 * GXH) {
        int4   ma = M[v];
        float4 pa = P[v];
        int4   mb = M[v + BT];
        float4 pb = P[v + BT];
        if (ma.x != 2) { localn++; atomicAdd(&sh[(score_key(pa.x, ma.x) >> 12) - B1_MIN], 1u); }
        if (ma.y != 2) { localn++; atomicAdd(&sh[(score_key(pa.y, ma.y) >> 12) - B1_MIN], 1u); }
        if (ma.z != 2) { localn++; atomicAdd(&sh[(score_key(pa.z, ma.z) >> 12) - B1_MIN], 1u); }
        if (ma.w != 2) { localn++; atomicAdd(&sh[(score_key(pa.w, ma.w) >> 12) - B1_MIN], 1u); }
        if (mb.x != 2) { localn++; atomicAdd(&sh[(score_key(pb.x, mb.x) >> 12) - B1_MIN], 1u); }
        if (mb.y != 2) { localn++; atomicAdd(&sh[(score_key(pb.y, mb.y) >> 12) - B1_MIN], 1u); }
        if (mb.z != 2) { localn++; atomicAdd(&sh[(score_key(pb.z, mb.z) >> 12) - B1_MIN], 1u); }
        if (mb.w != 2) { localn++; atomicAdd(&sh[(score_key(pb.w, mb.w) >> 12) - B1_MIN], 1u); }
    }
    atomicAdd(&scnt, localn);
    __syncthreads();
    for (int i = t; i < B1_BINS; i += BT) {
        unsigned v = sh[i];
        if (v) atomicAdd(&g_hist[b][i], v);
    }
    if (t == 0) atomicAdd(&g_np[b], scnt);
}

// ─── pass 2: per-batch threshold bin T + quota k1 (self-cleans hist) ───────
__global__ __launch_bounds__(1024) void k_select() {
    __shared__ unsigned s[1024];
    int b = blockIdx.x;
    int t = threadIdx.x;
    const int PB = 6;                 // 1024*6 >= 5249
    unsigned local = 0;
    unsigned hv[PB];
    #pragma unroll
    for (int j = 0; j < PB; j++) {
        int pos = t * PB + j;
        hv[j] = (pos < B1_BINS) ? g_hist[b][B1_BINS - 1 - pos] : 0u;  // descending
        local += hv[j];
    }
    s[t] = local; __syncthreads();
    for (int off = 1; off < 1024; off <<= 1) {
        unsigned v = (t >= off) ? s[t - off] : 0u;
        __syncthreads();
        s[t] += v;
        __syncthreads();
    }
    unsigned before = s[t] - local;
    unsigned np  = g_np[b];
    unsigned ntr = (unsigned)(int)((float)np * 0.5f);  // matches (f32(n)*0.5).astype(i32)
    if (t == 0) g_ntr[b] = ntr;
    if (ntr == 0) {
        if (t == 0) { g_T[b] = SENT; g_k1[b] = 0u; }
    } else if (before < ntr && before + local >= ntr) {
        unsigned acc = before;
        #pragma unroll
        for (int j = 0; j < PB; j++) {
            int pos = t * PB + j;
            if (pos >= B1_BINS) break;
            if (acc + hv[j] >= ntr) {
                g_T[b]  = (unsigned)(B1_BINS - 1 - pos);
                g_k1[b] = ntr - acc;
                break;
            }
            acc += hv[j];
        }
    }
    // self-clean for next replay
    __syncthreads();
    #pragma unroll
    for (int j = 0; j < PB; j++) {
        int pos = t * PB + j;
        if (pos < B1_BINS) g_hist[b][pos] = 0u;
    }
    if (t == 0) g_np[b] = 0u;
}

// ─── pass 3: fused final sweep — branchless uniform mask stores ────────────
// Candidates (bin==T) are provisionally stored as HOLDOUT (train=0, hold=1);
// k_refine flips the selected ones to train and adds their BCE.
__global__ __launch_bounds__(BT) void k_main(const float4* __restrict__ pred,
                                             const int4* __restrict__ mask,
                                             float* __restrict__ out) {
    int b = blockIdx.y;
    unsigned T = g_T[b];              // SENT => no train, no candidates
    const float4* P = pred + (size_t)b * HW4;
    const int4*   M = mask + (size_t)b * HW4;
    float* outT = out + 1 + (size_t)b * HW;
    float* outH = out + 1 + (size_t)BATCH * HW + (size_t)b * HW;

    double acc = 0.0;
    for (unsigned v = blockIdx.x * (BT * 2) + threadIdx.x; v < HW4; v += BT * 2 * GXM) {
        int4   m4[2];
        float4 p4[2];
        m4[0] = M[v];      p4[0] = P[v];
        m4[1] = M[v + BT]; p4[1] = P[v + BT];
        #pragma unroll
        for (int h = 0; h < 2; h++) {
            unsigned base = (v + h * BT) * 4u;
            #pragma unroll
            for (int k = 0; k < 4; k++) {
                int   m = (k == 0) ? m4[h].x : (k == 1) ? m4[h].y : (k == 2) ? m4[h].z : m4[h].w;
                float p = (k == 0) ? p4[h].x : (k == 1) ? p4[h].y : (k == 2) ? p4[h].z : p4[h].w;
                bool ann  = (m != 2);
                bool train = false;
                if (ann) {
                    unsigned key = score_key(p, m);
                    unsigned bin = (key >> 12) - B1_MIN;
                    train = bin > T;              // false when T == SENT
                    if (bin == T) {               // rare (~0.15% of elements)
                        unsigned pos = atomicAdd(&g_cnt[b], 1u);
                        if (pos < CAND_CAP) g_cand[b][pos] = make_uint2(key, base + k);
                    }
                }
                // candidates fall into the !train path -> provisional holdout=1
                __stcs(&outT[base + k], train ? 1.0f : 0.0f);
                __stcs(&outH[base + k], (ann && !train) ? 1.0f : 0.0f);
                if (train) {
                    float pc = fminf(fmaxf(p, 1e-7f), 1.0f - 1e-7f);
                    acc += (double)((m == 1) ? -logf(pc) : -logf(1.0f - pc));
                }
            }
        }
    }
    #pragma unroll
    for (int off = 16; off; off >>= 1)
        acc += __shfl_down_sync(0xFFFFFFFFu, acc, off);
    __shared__ double w[BT / 32];
    int lane = threadIdx.x & 31, warp = threadIdx.x >> 5;
    if (lane == 0) w[warp] = acc;
    __syncthreads();
    if (threadIdx.x == 0) {
        double s2 = 0.0;
        #pragma unroll
        for (int i = 0; i < BT / 32; i++) s2 += w[i];
        atomicAdd(&g_loss, s2);
    }
}

// ─── pass 4: exact cutoff in bin T, candidate fixups, finalize loss ────────
__global__ __launch_bounds__(256) void k_refine(const float* __restrict__ pred,
                                                const int* __restrict__ mask,
                                                float* __restrict__ out) {
    __shared__ unsigned h2[4096];
    __shared__ unsigned s[256];
    __shared__ unsigned eq[2048];
    __shared__ unsigned eqc;
    __shared__ unsigned shV, shKeq, shMeq, shIC;
    __shared__ double   w[8];
    __shared__ bool     lastb;
    int b = blockIdx.x;
    int t = threadIdx.x;
    unsigned T  = g_T[b];
    unsigned nc = min(g_cnt[b], (unsigned)CAND_CAP);  // all threads read BEFORE zeroing
    double acc = 0.0;
    __syncthreads();
    if (t == 0) g_cnt[b] = 0u;       // self-clean (nc captured above by all threads)

    if (T != SENT && nc > 0) {
        unsigned k1 = g_k1[b];
        if (t == 0) {
            eqc = 0u;
            shV = (T + B1_MIN) << 12;     // fallback
            shKeq = 0u; shMeq = 0u; shIC = SENT;
        }
        for (int i = t; i < 4096; i += 256) h2[i] = 0u;
        __syncthreads();
        for (unsigned i = t; i < nc; i += 256)
            atomicAdd(&h2[g_cand[b][i].x & 0xFFFu], 1u);
        __syncthreads();

        const int PB = 16;
        unsigned local = 0;
        #pragma unroll
        for (int j = 0; j < PB; j++) local += h2[4095 - (t * PB + j)];
        s[t] = local; __syncthreads();
        for (int off = 1; off < 256; off <<= 1) {
            unsigned v = (t >= off) ? s[t - off] : 0u;
            __syncthreads();
            s[t] += v;
            __syncthreads();
        }
        unsigned before = s[t] - local;
        if (before < k1 && before + local >= k1) {
            unsigned a2 = before;
            for (int j = 0; j < PB; j++) {
                int v = 4095 - (t * PB + j);
                unsigned h = h2[v];
                if (a2 + h >= k1) {
                    shV = ((T + B1_MIN) << 12) | (unsigned)v;
                    shKeq = k1 - a2; shMeq = h;
                    break;
                }
                a2 += h;
            }
        }
        __syncthreads();
        unsigned V = shV, keq = shKeq, meq = shMeq;
        if (keq != meq && meq != 0u) {
            // index tie-break among key==V (stable argsort: lowest idx wins)
            for (unsigned i = t; i < nc; i += 256) {
                if (g_cand[b][i].x == V) {
                    unsigned p = atomicAdd(&eqc, 1u);
                    if (p < 2048u) eq[p] = g_cand[b][i].y;
                }
            }
            __syncthreads();
            unsigned mm = min(eqc, 2048u);
            if (keq < mm) {
                for (unsigned i = t; i < mm; i += 256) {
                    unsigned x = eq[i], r = 0;
                    for (unsigned j = 0; j < mm; j++) r += (eq[j] < x) ? 1u : 0u;
                    if (r == keq) shIC = x;
                }
            }
            __syncthreads();
        }
        unsigned V2 = shV, ic = shIC;
        const float* Ps = pred + (size_t)b * HW;
        const int*   Ms = mask + (size_t)b * HW;
        float* outT = out + 1 + (size_t)b * HW;
        float* outH = out + 1 + (size_t)BATCH * HW + (size_t)b * HW;
        for (unsigned i = t; i < nc; i += 256) {
            uint2 c = g_cand[b][i];
            bool train = (c.x > V2) || (c.x == V2 && c.y < ic);
            if (train) {               // provisional value was holdout (T=0,H=1)
                outT[c.y] = 1.0f;
                outH[c.y] = 0.0f;
                float p = Ps[c.y];
                int   m = Ms[c.y];
                float pc = fminf(fmaxf(p, 1e-7f), 1.0f - 1e-7f);
                acc += (double)((m == 1) ? -logf(pc) : -logf(1.0f - pc));
            }
        }
    }

    // block reduce candidate BCE, then last-block finalization
    #pragma unroll
    for (int off = 16; off; off >>= 1)
        acc += __shfl_down_sync(0xFFFFFFFFu, acc, off);
    int lane = t & 31, warp = t >> 5;
    if (lane == 0) w[warp] = acc;
    __syncthreads();
    if (t == 0) {
        double s2 = 0.0;
        #pragma unroll
        for (int i = 0; i < 8; i++) s2 += w[i];
        if (s2 != 0.0) atomicAdd(&g_loss, s2);
        __threadfence();
        lastb = (atomicAdd(&g_done, 1u) == BATCH - 1u);
    }
    __syncthreads();
    if (lastb && t == 0) {
        __threadfence();
        unsigned tot = 0;
        #pragma unroll
        for (int i = 0; i < BATCH; i++) tot += g_ntr[i];
        out[0] = (float)g_loss / ((float)tot + 1e-7f);
        g_loss = 0.0;                  // self-clean for next replay
        g_done = 0u;
    }
}

extern "C" void kernel_launch(void* const* d_in, const int* in_sizes, int n_in,
                              void* d_out, int out_size) {
    const float4* pred = (const float4*)d_in[0];
    const int4*   mask = (const int4*)d_in[1];
    float* out = (float*)d_out;
    k_hist<<<dim3(GXH, BATCH), BT>>>(pred, mask);
    k_select<<<BATCH, 1024>>>();
    k_main<<<dim3(GXM, BATCH), BT>>>(pred, mask, out);
    k_refine<<<BATCH, 256>>>((const float*)d_in[0], (const int*)d_in[1], out);
}